// round 12
// baseline (speedup 1.0000x reference)
#include <cuda_runtime.h>
#include <cuda_fp16.h>
#include <cstdint>

#define Bsz 8
#define Ntok 1024
#define Cdim 768
#define Hh 12
#define HD 64
#define BH (Bsz*Hh)
#define SCALE 0.125f

// ======================= PTX helpers (sm_80+ baseline) ======================
__device__ __forceinline__ uint32_t smem_to_u32(const void* p) {
    uint32_t a;
    asm("{ .reg .u64 t; cvta.to.shared.u64 t, %1; cvt.u32.u64 %0, t; }" : "=r"(a) : "l"(p));
    return a;
}
#define LDSM4(r, addr) \
    asm volatile("ldmatrix.sync.aligned.m8n8.x4.shared.b16 {%0,%1,%2,%3}, [%4];" \
        : "=r"((r)[0]), "=r"((r)[1]), "=r"((r)[2]), "=r"((r)[3]) : "r"(addr))
#define MMA_F16(d, a, b) \
    asm volatile("mma.sync.aligned.m16n8k16.row.col.f32.f16.f16.f32 " \
        "{%0,%1,%2,%3}, {%4,%5,%6,%7}, {%8,%9}, {%0,%1,%2,%3};" \
        : "+f"((d)[0]), "+f"((d)[1]), "+f"((d)[2]), "+f"((d)[3]) \
        : "r"((a)[0]), "r"((a)[1]), "r"((a)[2]), "r"((a)[3]), "r"((b)[0]), "r"((b)[1]))
#define CP16(dst_u32, src_ptr) \
    asm volatile("cp.async.cg.shared.global [%0], [%1], 16;" :: "r"(dst_u32), "l"(src_ptr))
#define CP_COMMIT() asm volatile("cp.async.commit_group;")
#define CP_WAIT(n)  asm volatile("cp.async.wait_group %0;" :: "n"(n))

__device__ __forceinline__ uint32_t h2pack(float a, float b) {
    __half2 h = __floats2half2_rn(a, b);
    return *(uint32_t*)&h;
}

// ======================= scratch globals ====================================
__device__ __align__(16) __half g_x[3u * 8192u * 768u];   // xq|xk|xv fp16
__device__ __align__(16) __half g_w[4u * 768u * 768u];    // Wq|Wk|Wv|Wp fp16
__device__ __align__(16) __half g_q[8192u * 768u];        // flat [b*N+tok, c]
__device__ __align__(16) __half g_k[8192u * 768u];        // flat [b*N+tok, c]
__device__ __align__(16) __half g_vt[BH * HD * Ntok];     // [b,h,hd,tok]
__device__ __align__(16) __half g_o[8192u * 768u];        // attention out fp16
__device__ __align__(16) float g_aff[Bsz * Ntok];

// ======================= fp32 -> fp16 convert ===============================
__global__ void cvtX_kernel(const float4* __restrict__ s0, const float4* __restrict__ s1,
                            const float4* __restrict__ s2, int n4)
{
    int i = blockIdx.x * 256 + threadIdx.x;
    if (i >= n4) return;
    int z = blockIdx.z;
    const float4* src = (z == 0) ? s0 : (z == 1) ? s1 : s2;
    float4 v = src[i];
    size_t off = ((size_t)z * n4 + i) * 2;
    ((__half2*)g_x)[off]     = __floats2half2_rn(v.x, v.y);
    ((__half2*)g_x)[off + 1] = __floats2half2_rn(v.z, v.w);
}
__global__ void cvtW_kernel(const float4* __restrict__ s0, const float4* __restrict__ s1,
                            const float4* __restrict__ s2, const float4* __restrict__ s3, int n4)
{
    int i = blockIdx.x * 256 + threadIdx.x;
    if (i >= n4) return;
    int z = blockIdx.z;
    const float4* src = (z == 0) ? s0 : (z == 1) ? s1 : (z == 2) ? s2 : s3;
    float4 v = src[i];
    size_t off = ((size_t)z * n4 + i) * 2;
    ((__half2*)g_w)[off]     = __floats2half2_rn(v.x, v.y);
    ((__half2*)g_w)[off + 1] = __floats2half2_rn(v.z, v.w);
}

// ======================= single-term fp16 mma.sync GEMM (KC=64) =============
template <int BN>
__device__ __forceinline__ void gemm_to_stage(
    const __half* __restrict__ A, int lda,
    const __half* __restrict__ B, int ldb,
    int kTotal, char* smem)
{
    constexpr int SROW = 72;
    constexpr int A_0 = 0;
    constexpr int B_0 = 128 * SROW;
    constexpr int BUFH = (128 + BN) * SROW;
    constexpr int WN = BN / 2;
    constexpr int NT = BN / 16;
    constexpr int NTP = NT / 2;
    constexpr int NBJ = BN / 32;

    const uint32_t sbase = smem_to_u32(smem);
    const int tid = threadIdx.x, lane = tid & 31, wid = tid >> 5;
    const int wm = wid & 3, wn = wid >> 2;

    float acc[2][NT][4];
    #pragma unroll
    for (int i = 0; i < 2; i++)
        #pragma unroll
        for (int j = 0; j < NT; j++)
            #pragma unroll
            for (int l = 0; l < 4; l++) acc[i][j][l] = 0.f;

    auto CPA = [&](int buf, int k0) {
        uint32_t p = sbase + (uint32_t)buf * BUFH * 2u;
        #pragma unroll
        for (int j = 0; j < 4; j++) {
            int i = tid + j * 256, r = i >> 3, c = (i & 7) << 3;
            CP16(p + (A_0 + r * SROW + c) * 2, A + (size_t)r * lda + k0 + c);
        }
        #pragma unroll
        for (int j = 0; j < NBJ; j++) {
            int i = tid + j * 256, r = i >> 3, c = (i & 7) << 3;
            CP16(p + (B_0 + r * SROW + c) * 2, B + (size_t)r * ldb + k0 + c);
        }
        CP_COMMIT();
    };
    auto COMPUTE = [&](int buf) {
        const uint32_t base = sbase + (uint32_t)buf * BUFH * 2;
        #pragma unroll
        for (int ks = 0; ks < 64; ks += 16) {
            uint32_t af[2][4];
            const int arow = (lane & 7) + ((lane >> 3) & 1) * 8;
            const int acol = ks + (lane >> 4) * 8;
            #pragma unroll
            for (int mt = 0; mt < 2; mt++) {
                uint32_t off = (uint32_t)((wm * 32 + mt * 16 + arow) * SROW + acol) * 2;
                LDSM4(af[mt], base + A_0 * 2 + off);
            }
            uint32_t bf[NT][2];
            const int g = lane >> 3;
            const int brow = (g >> 1) * 8 + (lane & 7);
            const int bcol = ks + (g & 1) * 8;
            #pragma unroll
            for (int np = 0; np < NTP; np++) {
                uint32_t off = (uint32_t)((wn * WN + np * 16 + brow) * SROW + bcol) * 2;
                uint32_t t[4];
                LDSM4(t, base + B_0 * 2 + off);
                bf[2 * np][0] = t[0]; bf[2 * np][1] = t[1];
                bf[2 * np + 1][0] = t[2]; bf[2 * np + 1][1] = t[3];
            }
            #pragma unroll
            for (int mt = 0; mt < 2; mt++)
                #pragma unroll
                for (int nt = 0; nt < NT; nt++)
                    MMA_F16(acc[mt][nt], af[mt], bf[nt]);
        }
    };

    const int nCh = kTotal >> 6;
    CPA(0, 0);
    for (int ch = 0; ch < nCh; ch++) {
        if (ch + 1 < nCh) { CPA((ch + 1) & 1, (ch + 1) << 6); CP_WAIT(1); }
        else              { CP_WAIT(0); }
        __syncthreads();
        COMPUTE(ch & 1);
        __syncthreads();
    }

    float* stage = (float*)smem;
    const int gidr = lane >> 2, qid = lane & 3;
    #pragma unroll
    for (int mt = 0; mt < 2; mt++)
        #pragma unroll
        for (int nt = 0; nt < NT; nt++) {
            int row = wm * 32 + mt * 16 + gidr;
            int col = wn * WN + nt * 8 + qid * 2;
            stage[row * (BN + 1) + col]           = acc[mt][nt][0];
            stage[row * (BN + 1) + col + 1]       = acc[mt][nt][1];
            stage[(row + 8) * (BN + 1) + col]     = acc[mt][nt][2];
            stage[(row + 8) * (BN + 1) + col + 1] = acc[mt][nt][3];
        }
    __syncthreads();
}

// ======================= QKV projection (zoff selects q/k vs v) =============
__global__ void __launch_bounds__(256, 2) qkv_mma(int zoff)
{
    extern __shared__ char smem[];
    const int z = blockIdx.z + zoff;
    const int m0 = blockIdx.y * 128, n0 = blockIdx.x * 128;

    const __half* A = g_x + (size_t)z * 8192 * 768 + (size_t)m0 * 768;
    const __half* B = g_w + (size_t)z * 768 * 768 + (size_t)n0 * 768;

    gemm_to_stage<128>(A, 768, B, 768, 768, smem);
    float* stage = (float*)smem;

    const int tid = threadIdx.x;
    if (z < 2) {
        __half* dst = (z == 0) ? g_q : g_k;
        for (int idx = tid; idx < 128 * 64; idx += 256) {
            int mr = idx >> 6, nc = (idx & 63) * 2;
            *(__half2*)(dst + (size_t)(m0 + mr) * 768 + n0 + nc) =
                __floats2half2_rn(stage[mr * 129 + nc], stage[mr * 129 + nc + 1]);
        }
    } else {
        for (int idx = tid; idx < 128 * 64; idx += 256) {
            int t2 = idx & 63, nc = idx >> 6;
            int mr = t2 * 2;
            int m = m0 + mr, n = n0 + nc;
            int b = m >> 10, tok = m & 1023, h = n >> 6, hd = n & 63;
            size_t o = (((size_t)(b * Hh + h)) * HD + hd) * Ntok + tok;
            *(__half2*)(g_vt + o) =
                __floats2half2_rn(stage[mr * 129 + nc], stage[(mr + 1) * 129 + nc]);
        }
    }
}

// ======================= affinity gate ======================================
__global__ void aff_kernel(const float* __restrict__ et, float* __restrict__ out_aff)
{
    int warp = (blockIdx.x * blockDim.x + threadIdx.x) >> 5;
    int lane = threadIdx.x & 31;
    if (warp >= Bsz * Ntok) return;
    int b = warp >> 10;
    float s = 0.f;
    const __half* krow = g_k + (size_t)warp * 768;
    const float* erow = et + b * Cdim;
    for (int c = lane; c < Cdim; c += 32)
        s += erow[c] * __half2float(krow[c]);
    #pragma unroll
    for (int o = 16; o; o >>= 1) s += __shfl_xor_sync(0xffffffffu, s, o);
    if (lane == 0) {
        float v = 1.f / (1.f + __expf(-(SCALE / Hh) * s));
        g_aff[warp] = v;
        out_aff[warp] = v;
    }
}

// ======================= attn_save = (SCALE/H) * Qflat @ Kflat^T ============
__global__ void __launch_bounds__(256, 2) attnsave_mma(float* __restrict__ out_as)
{
    extern __shared__ char smem[];
    const int b = blockIdx.z;
    const int m0 = blockIdx.y * 128, n0 = blockIdx.x * 128;

    const __half* A = g_q + ((size_t)b * 1024 + m0) * 768;
    const __half* B = g_k + ((size_t)b * 1024 + n0) * 768;

    gemm_to_stage<128>(A, 768, B, 768, 768, smem);
    float* stage = (float*)smem;

    const float sc = SCALE / Hh;
    for (int idx = threadIdx.x; idx < 128 * 128; idx += 256) {
        int mr = idx >> 7, nc = idx & 127;
        out_as[((size_t)b * 1024 + m0 + mr) * 1024 + n0 + nc] = stage[mr * 129 + nc] * sc;
    }
}

// ======================= flash attention: FA2 register chaining =============
// 64 q-rows per CTA. Warps: wm in {0,1} (M 2x32), wn in {0..3} (k-slice 4x32).
// S acc -> exp -> fp16 A fragments in registers -> partial O over full N=64.
// Per-warp partial O accumulated across chunks; k-slice reduce once at end.
__global__ void __launch_bounds__(256, 2) flash_fused()
{
    extern __shared__ char smem[];
    constexpr int SRQ = 72;
    constexpr int SRV = 136;
    constexpr uint32_t Q_0 = 0;                      // 9216
    constexpr uint32_t K_0 = 9216;                   // 2 x 18432
    constexpr uint32_t KBUF = 128u * SRQ * 2u;
    constexpr uint32_t V_0 = 46080;                  // 2 x 17408
    constexpr uint32_t VBUF = 64u * SRV * 2u;
    constexpr uint32_t O_0 = 80896;                  // 64*65*4 = 16640
    constexpr uint32_t RS0 = 97536;                  // 64 floats

    const uint32_t sbase = smem_to_u32(smem);
    float* O_s = (float*)(smem + O_0);
    float* rowsum_s = (float*)(smem + RS0);

    const int z = blockIdx.y;
    const int m0 = blockIdx.x * 64;
    const int b = z / Hh, h = z % Hh;
    const int tid = threadIdx.x, lane = tid & 31, wid = tid >> 5;
    const int gidr = lane >> 2, qid = lane & 3;
    const int wm = wid & 1, wn = wid >> 1;

    const __half* Qg = g_q + ((size_t)b * 1024 + m0) * 768 + h * 64;
    const __half* Kg = g_k + (size_t)b * 1024 * 768 + h * 64;
    const __half* Vg = g_vt + (size_t)z * HD * Ntok;
    const float* aff = g_aff + b * 1024;

    // prologue loads: Q, K0, V0
    {
        int i = tid, r = i >> 3, c = (i & 7) << 3;
        CP16(sbase + Q_0 + (uint32_t)(r * SRQ + c) * 2, Qg + (size_t)r * 768 + c);
        i = tid + 256; r = i >> 3; c = (i & 7) << 3;
        CP16(sbase + Q_0 + (uint32_t)(r * SRQ + c) * 2, Qg + (size_t)r * 768 + c);
    }
    #pragma unroll
    for (int j = 0; j < 4; j++) {
        int i = tid + j * 256, r = i >> 3, c = (i & 7) << 3;
        CP16(sbase + K_0 + (uint32_t)(r * SRQ + c) * 2, Kg + (size_t)r * 768 + c);
    }
    #pragma unroll
    for (int j = 0; j < 4; j++) {
        int i = tid + j * 256, r = i >> 4, c = (i & 15) << 3;
        CP16(sbase + V_0 + (uint32_t)(r * SRV + c) * 2, Vg + (size_t)r * 1024 + c);
    }
    CP_COMMIT();
    if (tid < 64) rowsum_s[tid] = 0.f;
    for (int i = tid; i < 64 * 65; i += 256) O_s[i] = 0.f;

    float acc_o[2][8][4];
    #pragma unroll
    for (int i = 0; i < 2; i++)
        #pragma unroll
        for (int j = 0; j < 8; j++)
            #pragma unroll
            for (int l = 0; l < 4; l++) acc_o[i][j][l] = 0.f;

    for (int ch = 0; ch < 8; ch++) {
        const int k0 = ch * 128;
        const int kb = ch & 1;
        CP_WAIT(0);
        __syncthreads();

        // prefetch next K, V chunk
        if (ch + 1 < 8) {
            #pragma unroll
            for (int j = 0; j < 4; j++) {
                int i = tid + j * 256, r = i >> 3, c = (i & 7) << 3;
                CP16(sbase + K_0 + (kb ^ 1) * KBUF + (uint32_t)(r * SRQ + c) * 2,
                     Kg + (size_t)(k0 + 128 + r) * 768 + c);
            }
            #pragma unroll
            for (int j = 0; j < 4; j++) {
                int i = tid + j * 256, r = i >> 4, c = (i & 15) << 3;
                CP16(sbase + V_0 + (kb ^ 1) * VBUF + (uint32_t)(r * SRV + c) * 2,
                     Vg + (size_t)r * 1024 + k0 + 128 + c);
            }
            CP_COMMIT();
        }

        // ---- S = q @ k^T (M=64 via wm, this warp's 32-col slice via wn) ----
        float acc_s[2][4][4];
        #pragma unroll
        for (int i = 0; i < 2; i++)
            #pragma unroll
            for (int j = 0; j < 4; j++)
                #pragma unroll
                for (int l = 0; l < 4; l++) acc_s[i][j][l] = 0.f;

        const uint32_t kbase = sbase + K_0 + kb * KBUF;
        #pragma unroll
        for (int ks = 0; ks < 64; ks += 16) {
            uint32_t af[2][4];
            const int arow = (lane & 7) + ((lane >> 3) & 1) * 8;
            const int acol = ks + (lane >> 4) * 8;
            #pragma unroll
            for (int mt = 0; mt < 2; mt++) {
                uint32_t off = (uint32_t)((wm * 32 + mt * 16 + arow) * SRQ + acol) * 2;
                LDSM4(af[mt], sbase + Q_0 + off);
            }
            uint32_t bf[4][2];
            const int g = lane >> 3;
            const int brow = (g >> 1) * 8 + (lane & 7);
            const int bcol = ks + (g & 1) * 8;
            #pragma unroll
            for (int np = 0; np < 2; np++) {
                uint32_t off = (uint32_t)((wn * 32 + np * 16 + brow) * SRQ + bcol) * 2;
                uint32_t t[4];
                LDSM4(t, kbase + off);
                bf[2 * np][0] = t[0]; bf[2 * np][1] = t[1];
                bf[2 * np + 1][0] = t[2]; bf[2 * np + 1][1] = t[3];
            }
            #pragma unroll
            for (int mt = 0; mt < 2; mt++)
                #pragma unroll
                for (int nt = 0; nt < 4; nt++)
                    MMA_F16(acc_s[mt][nt], af[mt], bf[nt]);
        }

        // ---- exp(S*SCALE), rowsum (ungated), gate into acc_s ----
        float2 af2[4];
        #pragma unroll
        for (int nt = 0; nt < 4; nt++)
            af2[nt] = *(const float2*)(aff + k0 + wn * 32 + nt * 8 + qid * 2);
        #pragma unroll
        for (int mt = 0; mt < 2; mt++) {
            int row0 = wm * 32 + mt * 16 + gidr;
            float rs0 = 0.f, rs1 = 0.f;
            #pragma unroll
            for (int nt = 0; nt < 4; nt++) {
                float e0 = __expf(acc_s[mt][nt][0] * SCALE);
                float e1 = __expf(acc_s[mt][nt][1] * SCALE);
                float e2 = __expf(acc_s[mt][nt][2] * SCALE);
                float e3 = __expf(acc_s[mt][nt][3] * SCALE);
                rs0 += e0 + e1; rs1 += e2 + e3;
                acc_s[mt][nt][0] = e0 * af2[nt].x;
                acc_s[mt][nt][1] = e1 * af2[nt].y;
                acc_s[mt][nt][2] = e2 * af2[nt].x;
                acc_s[mt][nt][3] = e3 * af2[nt].y;
            }
            rs0 += __shfl_xor_sync(0xffffffffu, rs0, 1);
            rs0 += __shfl_xor_sync(0xffffffffu, rs0, 2);
            rs1 += __shfl_xor_sync(0xffffffffu, rs1, 1);
            rs1 += __shfl_xor_sync(0xffffffffu, rs1, 2);
            if (qid == 0) {
                atomicAdd(&rowsum_s[row0], rs0);
                atomicAdd(&rowsum_s[row0 + 8], rs1);
            }
        }

        // ---- O_partial += P(regs) @ V^T over this warp's k-slice ----
        const uint32_t vbase = sbase + V_0 + kb * VBUF;
        #pragma unroll
        for (int kg = 0; kg < 2; kg++) {
            uint32_t bf[8][2];
            const int g = lane >> 3;
            const int brow = (g >> 1) * 8 + (lane & 7);
            const int bcol = wn * 32 + kg * 16 + (g & 1) * 8;
            #pragma unroll
            for (int np = 0; np < 4; np++) {
                uint32_t off = (uint32_t)((np * 16 + brow) * SRV + bcol) * 2;
                uint32_t t[4];
                LDSM4(t, vbase + off);
                bf[2 * np][0] = t[0]; bf[2 * np][1] = t[1];
                bf[2 * np + 1][0] = t[2]; bf[2 * np + 1][1] = t[3];
            }
            #pragma unroll
            for (int mt = 0; mt < 2; mt++) {
                uint32_t a[4];
                a[0] = h2pack(acc_s[mt][2 * kg][0],     acc_s[mt][2 * kg][1]);
                a[1] = h2pack(acc_s[mt][2 * kg][2],     acc_s[mt][2 * kg][3]);
                a[2] = h2pack(acc_s[mt][2 * kg + 1][0], acc_s[mt][2 * kg + 1][1]);
                a[3] = h2pack(acc_s[mt][2 * kg + 1][2], acc_s[mt][2 * kg + 1][3]);
                #pragma unroll
                for (int nt = 0; nt < 8; nt++)
                    MMA_F16(acc_o[mt][nt], a, bf[nt]);
            }
        }
    }

    // ---- cross-warp k-slice reduction into O_s ----
    __syncthreads();
    #pragma unroll
    for (int mt = 0; mt < 2; mt++) {
        int row = wm * 32 + mt * 16 + gidr;
        #pragma unroll
        for (int nt = 0; nt < 8; nt++) {
            int col = nt * 8 + qid * 2;
            atomicAdd(&O_s[row * 65 + col],           acc_o[mt][nt][0]);
            atomicAdd(&O_s[row * 65 + col + 1],       acc_o[mt][nt][1]);
            atomicAdd(&O_s[(row + 8) * 65 + col],     acc_o[mt][nt][2]);
            atomicAdd(&O_s[(row + 8) * 65 + col + 1], acc_o[mt][nt][3]);
        }
    }
    __syncthreads();

    // ---- normalize, write fp16 ----
    for (int idx = tid; idx < 64 * 32; idx += 256) {
        int row = idx >> 5, cp = (idx & 31) * 2;
        float inv = 1.f / rowsum_s[row];
        size_t o = ((size_t)b * 1024 + m0 + row) * 768 + h * 64 + cp;
        *(__half2*)(g_o + o) =
            __floats2half2_rn(O_s[row * 65 + cp] * inv, O_s[row * 65 + cp + 1] * inv);
    }
}

// ======================= output projection ==================================
__global__ void __launch_bounds__(256, 2) proj_mma(const float* __restrict__ bp,
                                                   float* __restrict__ out)
{
    extern __shared__ char smem[];
    const int m0 = blockIdx.y * 128, n0 = blockIdx.x * 128;

    const __half* A = g_o + (size_t)m0 * 768;
    const __half* B = g_w + (size_t)3 * 768 * 768 + (size_t)n0 * 768;

    gemm_to_stage<128>(A, 768, B, 768, 768, smem);
    float* stage = (float*)smem;

    for (int idx = threadIdx.x; idx < 128 * 128; idx += 256) {
        int mr = idx >> 7, nc = idx & 127;
        int n = n0 + nc;
        out[(size_t)(m0 + mr) * Cdim + n] = stage[mr * 129 + nc] + bp[n];
    }
}

// ============================================================================
extern "C" void kernel_launch(void* const* d_in, const int* in_sizes, int n_in,
                              void* d_out, int out_size)
{
    (void)in_sizes; (void)n_in; (void)out_size;
    const float* xq = (const float*)d_in[0];
    const float* xk = (const float*)d_in[1];
    const float* xv = (const float*)d_in[2];
    const float* et = (const float*)d_in[3];
    const float* Wq = (const float*)d_in[4];
    const float* Wk = (const float*)d_in[5];
    const float* Wv = (const float*)d_in[6];
    const float* Wp = (const float*)d_in[7];
    const float* bp = (const float*)d_in[8];

    float* out     = (float*)d_out;
    float* out_x   = out;
    float* out_as  = out + (size_t)Bsz * Ntok * Cdim;
    float* out_aff = out_as + (size_t)Bsz * Ntok * Ntok;

    const int SMEM_BIG = 73728;
    const int SMEM_FLASH = 97792;
    cudaFuncSetAttribute(qkv_mma,      cudaFuncAttributeMaxDynamicSharedMemorySize, SMEM_BIG);
    cudaFuncSetAttribute(attnsave_mma, cudaFuncAttributeMaxDynamicSharedMemorySize, SMEM_BIG);
    cudaFuncSetAttribute(flash_fused,  cudaFuncAttributeMaxDynamicSharedMemorySize, SMEM_FLASH);
    cudaFuncSetAttribute(proj_mma,     cudaFuncAttributeMaxDynamicSharedMemorySize, SMEM_BIG);

    static cudaStream_t s1 = nullptr;
    static cudaEvent_t eQK = nullptr, eAff = nullptr, eA = nullptr;
    if (!s1) {
        cudaStreamCreateWithFlags(&s1, cudaStreamNonBlocking);
        cudaEventCreateWithFlags(&eQK, cudaEventDisableTiming);
        cudaEventCreateWithFlags(&eAff, cudaEventDisableTiming);
        cudaEventCreateWithFlags(&eA, cudaEventDisableTiming);
    }

    const int NX4 = 8192 * 768 / 4, NW4 = 768 * 768 / 4;
    cvtX_kernel<<<dim3((NX4 + 255) / 256, 1, 3), 256>>>((const float4*)xq, (const float4*)xk,
                                                        (const float4*)xv, NX4);
    cvtW_kernel<<<dim3((NW4 + 255) / 256, 1, 4), 256>>>((const float4*)Wq, (const float4*)Wk,
                                                        (const float4*)Wv, (const float4*)Wp, NW4);

    qkv_mma<<<dim3(6, 64, 2), 256, SMEM_BIG>>>(0);
    cudaEventRecord(eQK, 0);

    cudaStreamWaitEvent(s1, eQK, 0);
    aff_kernel<<<(Bsz * Ntok) / 8, 256, 0, s1>>>(et, out_aff);
    cudaEventRecord(eAff, s1);
    attnsave_mma<<<dim3(8, 8, Bsz), 256, SMEM_BIG, s1>>>(out_as);
    cudaEventRecord(eA, s1);

    qkv_mma<<<dim3(6, 64, 1), 256, SMEM_BIG>>>(2);
    cudaStreamWaitEvent(0, eAff, 0);
    flash_fused<<<dim3(16, BH), 256, SMEM_FLASH>>>();
    proj_mma<<<dim3(6, 64, 1), 256, SMEM_BIG>>>(bp, out_x);

    cudaStreamWaitEvent(0, eA, 0);
}

// round 14
// speedup vs baseline: 1.0346x; 1.0346x over previous
#include <cuda_runtime.h>
#include <cuda_fp16.h>
#include <cstdint>

#define Bsz 8
#define Ntok 1024
#define Cdim 768
#define Hh 12
#define HD 64
#define BH (Bsz*Hh)
#define SCALE 0.125f

// ======================= PTX helpers (sm_80+ baseline) ======================
__device__ __forceinline__ uint32_t smem_to_u32(const void* p) {
    uint32_t a;
    asm("{ .reg .u64 t; cvta.to.shared.u64 t, %1; cvt.u32.u64 %0, t; }" : "=r"(a) : "l"(p));
    return a;
}
#define LDSM4(r, addr) \
    asm volatile("ldmatrix.sync.aligned.m8n8.x4.shared.b16 {%0,%1,%2,%3}, [%4];" \
        : "=r"((r)[0]), "=r"((r)[1]), "=r"((r)[2]), "=r"((r)[3]) : "r"(addr))
#define MMA_F16(d, a, b) \
    asm volatile("mma.sync.aligned.m16n8k16.row.col.f32.f16.f16.f32 " \
        "{%0,%1,%2,%3}, {%4,%5,%6,%7}, {%8,%9}, {%0,%1,%2,%3};" \
        : "+f"((d)[0]), "+f"((d)[1]), "+f"((d)[2]), "+f"((d)[3]) \
        : "r"((a)[0]), "r"((a)[1]), "r"((a)[2]), "r"((a)[3]), "r"((b)[0]), "r"((b)[1]))
#define CP16(dst_u32, src_ptr) \
    asm volatile("cp.async.cg.shared.global [%0], [%1], 16;" :: "r"(dst_u32), "l"(src_ptr))
#define CP_COMMIT() asm volatile("cp.async.commit_group;")
#define CP_WAIT(n)  asm volatile("cp.async.wait_group %0;" :: "n"(n))

// ======================= scratch globals ====================================
__device__ __align__(16) __half g_x[3u * 8192u * 768u];   // xq|xk|xv fp16
__device__ __align__(16) __half g_w[4u * 768u * 768u];    // Wq|Wk|Wv|Wp fp16
__device__ __align__(16) __half g_q[8192u * 768u];        // flat [b*N+tok, c]
__device__ __align__(16) __half g_k[8192u * 768u];        // flat [b*N+tok, c]
__device__ __align__(16) __half g_vt[BH * HD * Ntok];     // [b,h,hd,tok]
__device__ __align__(16) __half g_o[8192u * 768u];        // attention out fp16
__device__ __align__(16) float g_aff[Bsz * Ntok];

// ======================= fp32 -> fp16 convert ===============================
__global__ void cvtX_kernel(const float4* __restrict__ s0, const float4* __restrict__ s1,
                            const float4* __restrict__ s2, int n4)
{
    int i = blockIdx.x * 256 + threadIdx.x;
    if (i >= n4) return;
    int z = blockIdx.z;
    const float4* src = (z == 0) ? s0 : (z == 1) ? s1 : s2;
    float4 v = src[i];
    size_t off = ((size_t)z * n4 + i) * 2;
    ((__half2*)g_x)[off]     = __floats2half2_rn(v.x, v.y);
    ((__half2*)g_x)[off + 1] = __floats2half2_rn(v.z, v.w);
}
__global__ void cvtW_kernel(const float4* __restrict__ s0, const float4* __restrict__ s1,
                            const float4* __restrict__ s2, const float4* __restrict__ s3, int n4)
{
    int i = blockIdx.x * 256 + threadIdx.x;
    if (i >= n4) return;
    int z = blockIdx.z;
    const float4* src = (z == 0) ? s0 : (z == 1) ? s1 : (z == 2) ? s2 : s3;
    float4 v = src[i];
    size_t off = ((size_t)z * n4 + i) * 2;
    ((__half2*)g_w)[off]     = __floats2half2_rn(v.x, v.y);
    ((__half2*)g_w)[off + 1] = __floats2half2_rn(v.z, v.w);
}

// ======================= single-term fp16 mma.sync GEMM =====================
// KC=64, 3-stage cp.async pipeline, ONE __syncthreads per chunk.
// C[128, BN] = A @ B^T. Result in SMEM stage, stride BN+1 floats. 256 threads.
template <int BN>
__device__ __forceinline__ void gemm_to_stage(
    const __half* __restrict__ A, int lda,
    const __half* __restrict__ B, int ldb,
    int kTotal, char* smem)
{
    constexpr int SROW = 72;                    // halves per row (64 + 8 pad)
    constexpr int A_0 = 0;
    constexpr int B_0 = 128 * SROW;
    constexpr int BUFH = (128 + BN) * SROW;
    constexpr int WN = BN / 2;
    constexpr int NT = BN / 16;
    constexpr int NTP = NT / 2;
    constexpr int NBJ = BN / 32;

    const uint32_t sbase = smem_to_u32(smem);
    const int tid = threadIdx.x, lane = tid & 31, wid = tid >> 5;
    const int wm = wid & 3, wn = wid >> 2;

    float acc[2][NT][4];
    #pragma unroll
    for (int i = 0; i < 2; i++)
        #pragma unroll
        for (int j = 0; j < NT; j++)
            #pragma unroll
            for (int l = 0; l < 4; l++) acc[i][j][l] = 0.f;

    auto CPA = [&](int buf, int k0) {
        uint32_t p = sbase + (uint32_t)buf * BUFH * 2u;
        #pragma unroll
        for (int j = 0; j < 4; j++) {
            int i = tid + j * 256, r = i >> 3, c = (i & 7) << 3;
            CP16(p + (A_0 + r * SROW + c) * 2, A + (size_t)r * lda + k0 + c);
        }
        #pragma unroll
        for (int j = 0; j < NBJ; j++) {
            int i = tid + j * 256, r = i >> 3, c = (i & 7) << 3;
            CP16(p + (B_0 + r * SROW + c) * 2, B + (size_t)r * ldb + k0 + c);
        }
        CP_COMMIT();
    };
    auto COMPUTE = [&](int buf) {
        const uint32_t base = sbase + (uint32_t)buf * BUFH * 2;
        #pragma unroll
        for (int ks = 0; ks < 64; ks += 16) {
            uint32_t af[2][4];
            const int arow = (lane & 7) + ((lane >> 3) & 1) * 8;
            const int acol = ks + (lane >> 4) * 8;
            #pragma unroll
            for (int mt = 0; mt < 2; mt++) {
                uint32_t off = (uint32_t)((wm * 32 + mt * 16 + arow) * SROW + acol) * 2;
                LDSM4(af[mt], base + A_0 * 2 + off);
            }
            uint32_t bf[NT][2];
            const int g = lane >> 3;
            const int brow = (g >> 1) * 8 + (lane & 7);
            const int bcol = ks + (g & 1) * 8;
            #pragma unroll
            for (int np = 0; np < NTP; np++) {
                uint32_t off = (uint32_t)((wn * WN + np * 16 + brow) * SROW + bcol) * 2;
                uint32_t t[4];
                LDSM4(t, base + B_0 * 2 + off);
                bf[2 * np][0] = t[0]; bf[2 * np][1] = t[1];
                bf[2 * np + 1][0] = t[2]; bf[2 * np + 1][1] = t[3];
            }
            #pragma unroll
            for (int mt = 0; mt < 2; mt++)
                #pragma unroll
                for (int nt = 0; nt < NT; nt++)
                    MMA_F16(acc[mt][nt], af[mt], bf[nt]);
        }
    };

    const int nCh = kTotal >> 6;
    CPA(0, 0);
    if (nCh > 1) CPA(1, 64);
    int buf = 0;
    for (int ch = 0; ch < nCh; ch++) {
        if (ch + 1 < nCh) { CP_WAIT(1); } else { CP_WAIT(0); }
        __syncthreads();
        if (ch + 2 < nCh) {
            int nb = buf + 2; if (nb >= 3) nb -= 3;
            CPA(nb, (ch + 2) << 6);
        }
        COMPUTE(buf);
        if (++buf == 3) buf = 0;
    }
    __syncthreads();

    float* stage = (float*)smem;
    const int gidr = lane >> 2, qid = lane & 3;
    #pragma unroll
    for (int mt = 0; mt < 2; mt++)
        #pragma unroll
        for (int nt = 0; nt < NT; nt++) {
            int row = wm * 32 + mt * 16 + gidr;
            int col = wn * WN + nt * 8 + qid * 2;
            stage[row * (BN + 1) + col]           = acc[mt][nt][0];
            stage[row * (BN + 1) + col + 1]       = acc[mt][nt][1];
            stage[(row + 8) * (BN + 1) + col]     = acc[mt][nt][2];
            stage[(row + 8) * (BN + 1) + col + 1] = acc[mt][nt][3];
        }
    __syncthreads();
}

// ======================= QKV projection (zoff selects q/k vs v) =============
__global__ void __launch_bounds__(256, 2) qkv_mma(int zoff)
{
    extern __shared__ char smem[];
    const int z = blockIdx.z + zoff;
    const int m0 = blockIdx.y * 128, n0 = blockIdx.x * 128;

    const __half* A = g_x + (size_t)z * 8192 * 768 + (size_t)m0 * 768;
    const __half* B = g_w + (size_t)z * 768 * 768 + (size_t)n0 * 768;

    gemm_to_stage<128>(A, 768, B, 768, 768, smem);
    float* stage = (float*)smem;

    const int tid = threadIdx.x;
    if (z < 2) {
        __half* dst = (z == 0) ? g_q : g_k;
        for (int idx = tid; idx < 128 * 64; idx += 256) {
            int mr = idx >> 6, nc = (idx & 63) * 2;
            *(__half2*)(dst + (size_t)(m0 + mr) * 768 + n0 + nc) =
                __floats2half2_rn(stage[mr * 129 + nc], stage[mr * 129 + nc + 1]);
        }
    } else {
        for (int idx = tid; idx < 128 * 64; idx += 256) {
            int t2 = idx & 63, nc = idx >> 6;
            int mr = t2 * 2;
            int m = m0 + mr, n = n0 + nc;
            int b = m >> 10, tok = m & 1023, h = n >> 6, hd = n & 63;
            size_t o = (((size_t)(b * Hh + h)) * HD + hd) * Ntok + tok;
            *(__half2*)(g_vt + o) =
                __floats2half2_rn(stage[mr * 129 + nc], stage[(mr + 1) * 129 + nc]);
        }
    }
}

// ======================= affinity gate ======================================
__global__ void aff_kernel(const float* __restrict__ et, float* __restrict__ out_aff)
{
    int warp = (blockIdx.x * blockDim.x + threadIdx.x) >> 5;
    int lane = threadIdx.x & 31;
    if (warp >= Bsz * Ntok) return;
    int b = warp >> 10;
    float s = 0.f;
    const __half* krow = g_k + (size_t)warp * 768;
    const float* erow = et + b * Cdim;
    for (int c = lane; c < Cdim; c += 32)
        s += erow[c] * __half2float(krow[c]);
    #pragma unroll
    for (int o = 16; o; o >>= 1) s += __shfl_xor_sync(0xffffffffu, s, o);
    if (lane == 0) {
        float v = 1.f / (1.f + __expf(-(SCALE / Hh) * s));
        g_aff[warp] = v;
        out_aff[warp] = v;
    }
}

// ======================= attn_save = (SCALE/H) * Qflat @ Kflat^T ============
__global__ void __launch_bounds__(256, 2) attnsave_mma(float* __restrict__ out_as)
{
    extern __shared__ char smem[];
    const int b = blockIdx.z;
    const int m0 = blockIdx.y * 128, n0 = blockIdx.x * 128;

    const __half* A = g_q + ((size_t)b * 1024 + m0) * 768;
    const __half* B = g_k + ((size_t)b * 1024 + n0) * 768;

    gemm_to_stage<128>(A, 768, B, 768, 768, smem);
    float* stage = (float*)smem;

    const float sc = SCALE / Hh;
    for (int idx = threadIdx.x; idx < 128 * 128; idx += 256) {
        int mr = idx >> 7, nc = idx & 127;
        out_as[((size_t)b * 1024 + m0 + mr) * 1024 + n0 + nc] = stage[mr * 129 + nc] * sc;
    }
}

// ======================= flash attention (R11 champion version) =============
__global__ void __launch_bounds__(256, 2) flash_fused()
{
    extern __shared__ char smem[];
    constexpr int SRQ = 72;
    constexpr int SRP = 136;
    constexpr uint32_t Q_0 = 0;
    constexpr uint32_t K_0 = 9216;
    constexpr uint32_t KBUF = 128u * SRQ * 2u;
    constexpr uint32_t V_0 = 46080;
    constexpr uint32_t P_0 = 63488;
    constexpr uint32_t RS0 = 80896;

    const uint32_t sbase = smem_to_u32(smem);
    __half* P_s = (__half*)(smem + P_0);
    float* rowsum_s = (float*)(smem + RS0);

    const int z = blockIdx.y;
    const int m0 = blockIdx.x * 64;
    const int b = z / Hh, h = z % Hh;
    const int tid = threadIdx.x, lane = tid & 31, wid = tid >> 5;
    const int gidr = lane >> 2, qid = lane & 3;
    const int wmS = wid & 1, wnS = wid >> 1;
    const int wm2 = wid & 1, wn2 = wid >> 1;

    const __half* Qg = g_q + ((size_t)b * 1024 + m0) * 768 + h * 64;
    const __half* Kg = g_k + (size_t)b * 1024 * 768 + h * 64;
    const __half* Vg = g_vt + (size_t)z * HD * Ntok;
    const float* aff = g_aff + b * 1024;

    {
        int i = tid, r = i >> 3, c = (i & 7) << 3;
        CP16(sbase + Q_0 + (uint32_t)(r * SRQ + c) * 2, Qg + (size_t)r * 768 + c);
        i = tid + 256; r = i >> 3; c = (i & 7) << 3;
        CP16(sbase + Q_0 + (uint32_t)(r * SRQ + c) * 2, Qg + (size_t)r * 768 + c);
    }
    #pragma unroll
    for (int j = 0; j < 4; j++) {
        int i = tid + j * 256, r = i >> 3, c = (i & 7) << 3;
        CP16(sbase + K_0 + (uint32_t)(r * SRQ + c) * 2, Kg + (size_t)r * 768 + c);
    }
    #pragma unroll
    for (int j = 0; j < 4; j++) {
        int i = tid + j * 256, r = i >> 4, c = (i & 15) << 3;
        CP16(sbase + V_0 + (uint32_t)(r * SRP + c) * 2, Vg + (size_t)r * 1024 + c);
    }
    CP_COMMIT();
    if (tid < 64) rowsum_s[tid] = 0.f;

    float acc_o[2][2][4];
    #pragma unroll
    for (int i = 0; i < 2; i++)
        #pragma unroll
        for (int j = 0; j < 2; j++)
            #pragma unroll
            for (int l = 0; l < 4; l++) acc_o[i][j][l] = 0.f;

    for (int ch = 0; ch < 8; ch++) {
        const int k0 = ch * 128;
        const int kb = ch & 1;
        CP_WAIT(0);
        __syncthreads();

        if (ch + 1 < 8) {
            #pragma unroll
            for (int j = 0; j < 4; j++) {
                int i = tid + j * 256, r = i >> 3, c = (i & 7) << 3;
                CP16(sbase + K_0 + (kb ^ 1) * KBUF + (uint32_t)(r * SRQ + c) * 2,
                     Kg + (size_t)(k0 + 128 + r) * 768 + c);
            }
            CP_COMMIT();
        }

        float acc_s[2][4][4];
        #pragma unroll
        for (int i = 0; i < 2; i++)
            #pragma unroll
            for (int j = 0; j < 4; j++)
                #pragma unroll
                for (int l = 0; l < 4; l++) acc_s[i][j][l] = 0.f;

        const uint32_t kbase = sbase + K_0 + kb * KBUF;
        #pragma unroll
        for (int ks = 0; ks < 64; ks += 16) {
            uint32_t af[2][4];
            const int arow = (lane & 7) + ((lane >> 3) & 1) * 8;
            const int acol = ks + (lane >> 4) * 8;
            #pragma unroll
            for (int mt = 0; mt < 2; mt++) {
                uint32_t off = (uint32_t)((wmS * 32 + mt * 16 + arow) * SRQ + acol) * 2;
                LDSM4(af[mt], sbase + Q_0 + off);
            }
            uint32_t bf[4][2];
            const int g = lane >> 3;
            const int brow = (g >> 1) * 8 + (lane & 7);
            const int bcol = ks + (g & 1) * 8;
            #pragma unroll
            for (int np = 0; np < 2; np++) {
                uint32_t off = (uint32_t)((wnS * 32 + np * 16 + brow) * SRQ + bcol) * 2;
                uint32_t t[4];
                LDSM4(t, kbase + off);
                bf[2 * np][0] = t[0]; bf[2 * np][1] = t[1];
                bf[2 * np + 1][0] = t[2]; bf[2 * np + 1][1] = t[3];
            }
            #pragma unroll
            for (int mt = 0; mt < 2; mt++)
                #pragma unroll
                for (int nt = 0; nt < 4; nt++)
                    MMA_F16(acc_s[mt][nt], af[mt], bf[nt]);
        }

        float2 af2[4];
        #pragma unroll
        for (int nt = 0; nt < 4; nt++)
            af2[nt] = *(const float2*)(aff + k0 + wnS * 32 + nt * 8 + qid * 2);
        #pragma unroll
        for (int mt = 0; mt < 2; mt++) {
            int row0 = wmS * 32 + mt * 16 + gidr;
            float rs0 = 0.f, rs1 = 0.f;
            #pragma unroll
            for (int nt = 0; nt < 4; nt++) {
                float e0 = __expf(acc_s[mt][nt][0] * SCALE);
                float e1 = __expf(acc_s[mt][nt][1] * SCALE);
                float e2 = __expf(acc_s[mt][nt][2] * SCALE);
                float e3 = __expf(acc_s[mt][nt][3] * SCALE);
                rs0 += e0 + e1; rs1 += e2 + e3;
                int col = wnS * 32 + nt * 8 + qid * 2;
                *(__half2*)(P_s + row0 * SRP + col)       = __floats2half2_rn(e0 * af2[nt].x, e1 * af2[nt].y);
                *(__half2*)(P_s + (row0 + 8) * SRP + col) = __floats2half2_rn(e2 * af2[nt].x, e3 * af2[nt].y);
            }
            rs0 += __shfl_xor_sync(0xffffffffu, rs0, 1);
            rs0 += __shfl_xor_sync(0xffffffffu, rs0, 2);
            rs1 += __shfl_xor_sync(0xffffffffu, rs1, 1);
            rs1 += __shfl_xor_sync(0xffffffffu, rs1, 2);
            if (qid == 0) {
                atomicAdd(&rowsum_s[row0], rs0);
                atomicAdd(&rowsum_s[row0 + 8], rs1);
            }
        }
        __syncthreads();

        #pragma unroll
        for (int ks = 0; ks < 128; ks += 16) {
            uint32_t af[2][4];
            const int arow = (lane & 7) + ((lane >> 3) & 1) * 8;
            const int acol = ks + (lane >> 4) * 8;
            #pragma unroll
            for (int mt = 0; mt < 2; mt++) {
                uint32_t off = (uint32_t)((wm2 * 32 + mt * 16 + arow) * SRP + acol) * 2;
                LDSM4(af[mt], sbase + P_0 + off);
            }
            uint32_t bf[2][2];
            const int g = lane >> 3;
            const int brow = (g >> 1) * 8 + (lane & 7);
            const int bcol = ks + (g & 1) * 8;
            {
                uint32_t off = (uint32_t)((wn2 * 16 + brow) * SRP + bcol) * 2;
                uint32_t t[4];
                LDSM4(t, sbase + V_0 + off);
                bf[0][0] = t[0]; bf[0][1] = t[1]; bf[1][0] = t[2]; bf[1][1] = t[3];
            }
            #pragma unroll
            for (int mt = 0; mt < 2; mt++)
                #pragma unroll
                for (int nt = 0; nt < 2; nt++)
                    MMA_F16(acc_o[mt][nt], af[mt], bf[nt]);
        }
        __syncthreads();

        if (ch + 1 < 8) {
            #pragma unroll
            for (int j = 0; j < 4; j++) {
                int i = tid + j * 256, r = i >> 4, c = (i & 15) << 3;
                CP16(sbase + V_0 + (uint32_t)(r * SRP + c) * 2, Vg + (size_t)r * 1024 + k0 + 128 + c);
            }
            CP_COMMIT();
        }
    }

    #pragma unroll
    for (int mt = 0; mt < 2; mt++) {
        int row = wm2 * 32 + mt * 16 + gidr;
        float inv0 = 1.f / rowsum_s[row];
        float inv8 = 1.f / rowsum_s[row + 8];
        #pragma unroll
        for (int nt = 0; nt < 2; nt++) {
            int col = wn2 * 16 + nt * 8 + qid * 2;
            size_t o0 = ((size_t)b * 1024 + m0 + row) * 768 + h * 64 + col;
            size_t o8 = o0 + 8u * 768u;
            *(__half2*)(g_o + o0) = __floats2half2_rn(acc_o[mt][nt][0] * inv0, acc_o[mt][nt][1] * inv0);
            *(__half2*)(g_o + o8) = __floats2half2_rn(acc_o[mt][nt][2] * inv8, acc_o[mt][nt][3] * inv8);
        }
    }
}

// ======================= output projection ==================================
__global__ void __launch_bounds__(256, 2) proj_mma(const float* __restrict__ bp,
                                                   float* __restrict__ out)
{
    extern __shared__ char smem[];
    const int m0 = blockIdx.y * 128, n0 = blockIdx.x * 128;

    const __half* A = g_o + (size_t)m0 * 768;
    const __half* B = g_w + (size_t)3 * 768 * 768 + (size_t)n0 * 768;

    gemm_to_stage<128>(A, 768, B, 768, 768, smem);
    float* stage = (float*)smem;

    for (int idx = threadIdx.x; idx < 128 * 128; idx += 256) {
        int mr = idx >> 7, nc = idx & 127;
        int n = n0 + nc;
        out[(size_t)(m0 + mr) * Cdim + n] = stage[mr * 129 + nc] + bp[n];
    }
}

// ============================================================================
extern "C" void kernel_launch(void* const* d_in, const int* in_sizes, int n_in,
                              void* d_out, int out_size)
{
    (void)in_sizes; (void)n_in; (void)out_size;
    const float* xq = (const float*)d_in[0];
    const float* xk = (const float*)d_in[1];
    const float* xv = (const float*)d_in[2];
    const float* et = (const float*)d_in[3];
    const float* Wq = (const float*)d_in[4];
    const float* Wk = (const float*)d_in[5];
    const float* Wv = (const float*)d_in[6];
    const float* Wp = (const float*)d_in[7];
    const float* bp = (const float*)d_in[8];

    float* out     = (float*)d_out;
    float* out_x   = out;
    float* out_as  = out + (size_t)Bsz * Ntok * Cdim;
    float* out_aff = out_as + (size_t)Bsz * Ntok * Ntok;

    const int SMEM_BIG = 110592;   // 3 x (128+128)*72*2 bufs; stage 66048 fits
    const int SMEM_FLASH = 81152;
    cudaFuncSetAttribute(qkv_mma,      cudaFuncAttributeMaxDynamicSharedMemorySize, SMEM_BIG);
    cudaFuncSetAttribute(attnsave_mma, cudaFuncAttributeMaxDynamicSharedMemorySize, SMEM_BIG);
    cudaFuncSetAttribute(flash_fused,  cudaFuncAttributeMaxDynamicSharedMemorySize, SMEM_FLASH);
    cudaFuncSetAttribute(proj_mma,     cudaFuncAttributeMaxDynamicSharedMemorySize, SMEM_BIG);

    static cudaStream_t s1 = nullptr;
    static cudaEvent_t eQK = nullptr, eAff = nullptr, eA = nullptr;
    if (!s1) {
        cudaStreamCreateWithFlags(&s1, cudaStreamNonBlocking);
        cudaEventCreateWithFlags(&eQK, cudaEventDisableTiming);
        cudaEventCreateWithFlags(&eAff, cudaEventDisableTiming);
        cudaEventCreateWithFlags(&eA, cudaEventDisableTiming);
    }

    const int NX4 = 8192 * 768 / 4, NW4 = 768 * 768 / 4;
    // all pre-fork work on the capture-origin stream (R12-legal topology)
    cvtX_kernel<<<dim3((NX4 + 255) / 256, 1, 3), 256>>>((const float4*)xq, (const float4*)xk,
                                                        (const float4*)xv, NX4);
    cvtW_kernel<<<dim3((NW4 + 255) / 256, 1, 4), 256>>>((const float4*)Wq, (const float4*)Wk,
                                                        (const float4*)Wv, (const float4*)Wp, NW4);

    qkv_mma<<<dim3(6, 64, 2), 256, SMEM_BIG>>>(0);
    cudaEventRecord(eQK, 0);

    // fork AFTER eQK (legal: s1 joins capture via wait on captured event)
    cudaStreamWaitEvent(s1, eQK, 0);
    aff_kernel<<<(Bsz * Ntok) / 8, 256, 0, s1>>>(et, out_aff);
    cudaEventRecord(eAff, s1);
    attnsave_mma<<<dim3(8, 8, Bsz), 256, SMEM_BIG, s1>>>(out_as);
    cudaEventRecord(eA, s1);

    qkv_mma<<<dim3(6, 64, 1), 256, SMEM_BIG>>>(2);
    cudaStreamWaitEvent(0, eAff, 0);
    flash_fused<<<dim3(16, BH), 256, SMEM_FLASH>>>();
    proj_mma<<<dim3(6, 64, 1), 256, SMEM_BIG>>>(bp, out_x);

    cudaStreamWaitEvent(0, eA, 0);
}

// round 15
// speedup vs baseline: 1.0881x; 1.0517x over previous
#include <cuda_runtime.h>
#include <cuda_fp16.h>
#include <cstdint>

#define Bsz 8
#define Ntok 1024
#define Cdim 768
#define Hh 12
#define HD 64
#define BH (Bsz*Hh)
#define SCALE 0.125f

// ======================= PTX helpers (sm_80+ baseline) ======================
__device__ __forceinline__ uint32_t smem_to_u32(const void* p) {
    uint32_t a;
    asm("{ .reg .u64 t; cvta.to.shared.u64 t, %1; cvt.u32.u64 %0, t; }" : "=r"(a) : "l"(p));
    return a;
}
#define LDSM4(r, addr) \
    asm volatile("ldmatrix.sync.aligned.m8n8.x4.shared.b16 {%0,%1,%2,%3}, [%4];" \
        : "=r"((r)[0]), "=r"((r)[1]), "=r"((r)[2]), "=r"((r)[3]) : "r"(addr))
#define MMA_F16(d, a, b) \
    asm volatile("mma.sync.aligned.m16n8k16.row.col.f32.f16.f16.f32 " \
        "{%0,%1,%2,%3}, {%4,%5,%6,%7}, {%8,%9}, {%0,%1,%2,%3};" \
        : "+f"((d)[0]), "+f"((d)[1]), "+f"((d)[2]), "+f"((d)[3]) \
        : "r"((a)[0]), "r"((a)[1]), "r"((a)[2]), "r"((a)[3]), "r"((b)[0]), "r"((b)[1]))
#define CP16(dst_u32, src_ptr) \
    asm volatile("cp.async.cg.shared.global [%0], [%1], 16;" :: "r"(dst_u32), "l"(src_ptr))
#define CP_COMMIT() asm volatile("cp.async.commit_group;")
#define CP_WAIT(n)  asm volatile("cp.async.wait_group %0;" :: "n"(n))

// ======================= scratch globals ====================================
__device__ __align__(16) __half g_x[3u * 8192u * 768u];   // xq|xk|xv fp16
__device__ __align__(16) __half g_w[4u * 768u * 768u];    // Wq|Wk|Wv|Wp fp16
__device__ __align__(16) __half g_q[8192u * 768u];        // flat [b*N+tok, c]
__device__ __align__(16) __half g_k[8192u * 768u];        // flat [b*N+tok, c]
__device__ __align__(16) __half g_vt[BH * HD * Ntok];     // [b,h,hd,tok]
__device__ __align__(16) __half g_o[8192u * 768u];        // attention out fp16
__device__ __align__(16) float g_aff[Bsz * Ntok];

// ======================= fp32 -> fp16 convert ===============================
__global__ void cvtX_kernel(const float4* __restrict__ s0, const float4* __restrict__ s1,
                            const float4* __restrict__ s2, int n4)
{
    int i = blockIdx.x * 256 + threadIdx.x;
    if (i >= n4) return;
    int z = blockIdx.z;
    const float4* src = (z == 0) ? s0 : (z == 1) ? s1 : s2;
    float4 v = src[i];
    size_t off = ((size_t)z * n4 + i) * 2;
    ((__half2*)g_x)[off]     = __floats2half2_rn(v.x, v.y);
    ((__half2*)g_x)[off + 1] = __floats2half2_rn(v.z, v.w);
}
__global__ void cvtW_kernel(const float4* __restrict__ s0, const float4* __restrict__ s1,
                            const float4* __restrict__ s2, const float4* __restrict__ s3, int n4)
{
    int i = blockIdx.x * 256 + threadIdx.x;
    if (i >= n4) return;
    int z = blockIdx.z;
    const float4* src = (z == 0) ? s0 : (z == 1) ? s1 : (z == 2) ? s2 : s3;
    float4 v = src[i];
    size_t off = ((size_t)z * n4 + i) * 2;
    ((__half2*)g_w)[off]     = __floats2half2_rn(v.x, v.y);
    ((__half2*)g_w)[off + 1] = __floats2half2_rn(v.z, v.w);
}

// ======================= single-term fp16 mma.sync GEMM =====================
// KC=64, 3-stage cp.async pipeline, ONE __syncthreads per chunk.
template <int BN>
__device__ __forceinline__ void gemm_to_stage(
    const __half* __restrict__ A, int lda,
    const __half* __restrict__ B, int ldb,
    int kTotal, char* smem)
{
    constexpr int SROW = 72;
    constexpr int A_0 = 0;
    constexpr int B_0 = 128 * SROW;
    constexpr int BUFH = (128 + BN) * SROW;
    constexpr int WN = BN / 2;
    constexpr int NT = BN / 16;
    constexpr int NTP = NT / 2;
    constexpr int NBJ = BN / 32;

    const uint32_t sbase = smem_to_u32(smem);
    const int tid = threadIdx.x, lane = tid & 31, wid = tid >> 5;
    const int wm = wid & 3, wn = wid >> 2;

    float acc[2][NT][4];
    #pragma unroll
    for (int i = 0; i < 2; i++)
        #pragma unroll
        for (int j = 0; j < NT; j++)
            #pragma unroll
            for (int l = 0; l < 4; l++) acc[i][j][l] = 0.f;

    auto CPA = [&](int buf, int k0) {
        uint32_t p = sbase + (uint32_t)buf * BUFH * 2u;
        #pragma unroll
        for (int j = 0; j < 4; j++) {
            int i = tid + j * 256, r = i >> 3, c = (i & 7) << 3;
            CP16(p + (A_0 + r * SROW + c) * 2, A + (size_t)r * lda + k0 + c);
        }
        #pragma unroll
        for (int j = 0; j < NBJ; j++) {
            int i = tid + j * 256, r = i >> 3, c = (i & 7) << 3;
            CP16(p + (B_0 + r * SROW + c) * 2, B + (size_t)r * ldb + k0 + c);
        }
        CP_COMMIT();
    };
    auto COMPUTE = [&](int buf) {
        const uint32_t base = sbase + (uint32_t)buf * BUFH * 2;
        #pragma unroll
        for (int ks = 0; ks < 64; ks += 16) {
            uint32_t af[2][4];
            const int arow = (lane & 7) + ((lane >> 3) & 1) * 8;
            const int acol = ks + (lane >> 4) * 8;
            #pragma unroll
            for (int mt = 0; mt < 2; mt++) {
                uint32_t off = (uint32_t)((wm * 32 + mt * 16 + arow) * SROW + acol) * 2;
                LDSM4(af[mt], base + A_0 * 2 + off);
            }
            uint32_t bf[NT][2];
            const int g = lane >> 3;
            const int brow = (g >> 1) * 8 + (lane & 7);
            const int bcol = ks + (g & 1) * 8;
            #pragma unroll
            for (int np = 0; np < NTP; np++) {
                uint32_t off = (uint32_t)((wn * WN + np * 16 + brow) * SROW + bcol) * 2;
                uint32_t t[4];
                LDSM4(t, base + B_0 * 2 + off);
                bf[2 * np][0] = t[0]; bf[2 * np][1] = t[1];
                bf[2 * np + 1][0] = t[2]; bf[2 * np + 1][1] = t[3];
            }
            #pragma unroll
            for (int mt = 0; mt < 2; mt++)
                #pragma unroll
                for (int nt = 0; nt < NT; nt++)
                    MMA_F16(acc[mt][nt], af[mt], bf[nt]);
        }
    };

    const int nCh = kTotal >> 6;
    CPA(0, 0);
    if (nCh > 1) CPA(1, 64);
    int buf = 0;
    for (int ch = 0; ch < nCh; ch++) {
        if (ch + 1 < nCh) { CP_WAIT(1); } else { CP_WAIT(0); }
        __syncthreads();
        if (ch + 2 < nCh) {
            int nb = buf + 2; if (nb >= 3) nb -= 3;
            CPA(nb, (ch + 2) << 6);
        }
        COMPUTE(buf);
        if (++buf == 3) buf = 0;
    }
    __syncthreads();

    float* stage = (float*)smem;
    const int gidr = lane >> 2, qid = lane & 3;
    #pragma unroll
    for (int mt = 0; mt < 2; mt++)
        #pragma unroll
        for (int nt = 0; nt < NT; nt++) {
            int row = wm * 32 + mt * 16 + gidr;
            int col = wn * WN + nt * 8 + qid * 2;
            stage[row * (BN + 1) + col]           = acc[mt][nt][0];
            stage[row * (BN + 1) + col + 1]       = acc[mt][nt][1];
            stage[(row + 8) * (BN + 1) + col]     = acc[mt][nt][2];
            stage[(row + 8) * (BN + 1) + col + 1] = acc[mt][nt][3];
        }
    __syncthreads();
}

// ======================= QKV projection (zoff selects q/k vs v) =============
__global__ void __launch_bounds__(256, 2) qkv_mma(int zoff)
{
    extern __shared__ char smem[];
    const int z = blockIdx.z + zoff;
    const int m0 = blockIdx.y * 128, n0 = blockIdx.x * 128;

    const __half* A = g_x + (size_t)z * 8192 * 768 + (size_t)m0 * 768;
    const __half* B = g_w + (size_t)z * 768 * 768 + (size_t)n0 * 768;

    gemm_to_stage<128>(A, 768, B, 768, 768, smem);
    float* stage = (float*)smem;

    const int tid = threadIdx.x;
    if (z < 2) {
        __half* dst = (z == 0) ? g_q : g_k;
        for (int idx = tid; idx < 128 * 64; idx += 256) {
            int mr = idx >> 6, nc = (idx & 63) * 2;
            *(__half2*)(dst + (size_t)(m0 + mr) * 768 + n0 + nc) =
                __floats2half2_rn(stage[mr * 129 + nc], stage[mr * 129 + nc + 1]);
        }
    } else {
        for (int idx = tid; idx < 128 * 64; idx += 256) {
            int t2 = idx & 63, nc = idx >> 6;
            int mr = t2 * 2;
            int m = m0 + mr, n = n0 + nc;
            int b = m >> 10, tok = m & 1023, h = n >> 6, hd = n & 63;
            size_t o = (((size_t)(b * Hh + h)) * HD + hd) * Ntok + tok;
            *(__half2*)(g_vt + o) =
                __floats2half2_rn(stage[mr * 129 + nc], stage[(mr + 1) * 129 + nc]);
        }
    }
}

// ======================= affinity gate ======================================
__global__ void aff_kernel(const float* __restrict__ et, float* __restrict__ out_aff)
{
    int warp = (blockIdx.x * blockDim.x + threadIdx.x) >> 5;
    int lane = threadIdx.x & 31;
    if (warp >= Bsz * Ntok) return;
    int b = warp >> 10;
    float s = 0.f;
    const __half* krow = g_k + (size_t)warp * 768;
    const float* erow = et + b * Cdim;
    for (int c = lane; c < Cdim; c += 32)
        s += erow[c] * __half2float(krow[c]);
    #pragma unroll
    for (int o = 16; o; o >>= 1) s += __shfl_xor_sync(0xffffffffu, s, o);
    if (lane == 0) {
        float v = 1.f / (1.f + __expf(-(SCALE / Hh) * s));
        g_aff[warp] = v;
        out_aff[warp] = v;
    }
}

// ======================= attn_save = (SCALE/H) * Qflat @ Kflat^T ============
__global__ void __launch_bounds__(256, 2) attnsave_mma(float* __restrict__ out_as)
{
    extern __shared__ char smem[];
    const int b = blockIdx.z;
    const int m0 = blockIdx.y * 128, n0 = blockIdx.x * 128;

    const __half* A = g_q + ((size_t)b * 1024 + m0) * 768;
    const __half* B = g_k + ((size_t)b * 1024 + n0) * 768;

    gemm_to_stage<128>(A, 768, B, 768, 768, smem);
    float* stage = (float*)smem;

    const float sc = SCALE / Hh;
    for (int idx = threadIdx.x; idx < 128 * 128; idx += 256) {
        int mr = idx >> 7, nc = idx & 127;
        out_as[((size_t)b * 1024 + m0 + mr) * 1024 + n0 + nc] = stage[mr * 129 + nc] * sc;
    }
}

// ======================= flash attention (Q-frag hoist + rowsum banks) ======
__global__ void __launch_bounds__(256, 2) flash_fused()
{
    extern __shared__ char smem[];
    constexpr int SRQ = 72;
    constexpr int SRP = 136;
    constexpr uint32_t Q_0 = 0;
    constexpr uint32_t K_0 = 9216;
    constexpr uint32_t KBUF = 128u * SRQ * 2u;
    constexpr uint32_t V_0 = 46080;
    constexpr uint32_t P_0 = 63488;
    constexpr uint32_t RS0 = 80896;                  // 4 banks x 64 floats

    const uint32_t sbase = smem_to_u32(smem);
    __half* P_s = (__half*)(smem + P_0);
    float* rowsum_s = (float*)(smem + RS0);

    const int z = blockIdx.y;
    const int m0 = blockIdx.x * 64;
    const int b = z / Hh, h = z % Hh;
    const int tid = threadIdx.x, lane = tid & 31, wid = tid >> 5;
    const int gidr = lane >> 2, qid = lane & 3;
    const int wmS = wid & 1, wnS = wid >> 1;
    const int wm2 = wid & 1, wn2 = wid >> 1;

    const __half* Qg = g_q + ((size_t)b * 1024 + m0) * 768 + h * 64;
    const __half* Kg = g_k + (size_t)b * 1024 * 768 + h * 64;
    const __half* Vg = g_vt + (size_t)z * HD * Ntok;
    const float* aff = g_aff + b * 1024;

    {
        int i = tid, r = i >> 3, c = (i & 7) << 3;
        CP16(sbase + Q_0 + (uint32_t)(r * SRQ + c) * 2, Qg + (size_t)r * 768 + c);
        i = tid + 256; r = i >> 3; c = (i & 7) << 3;
        CP16(sbase + Q_0 + (uint32_t)(r * SRQ + c) * 2, Qg + (size_t)r * 768 + c);
    }
    #pragma unroll
    for (int j = 0; j < 4; j++) {
        int i = tid + j * 256, r = i >> 3, c = (i & 7) << 3;
        CP16(sbase + K_0 + (uint32_t)(r * SRQ + c) * 2, Kg + (size_t)r * 768 + c);
    }
    #pragma unroll
    for (int j = 0; j < 4; j++) {
        int i = tid + j * 256, r = i >> 4, c = (i & 15) << 3;
        CP16(sbase + V_0 + (uint32_t)(r * SRP + c) * 2, Vg + (size_t)r * 1024 + c);
    }
    CP_COMMIT();
    if (tid < 64) {
        rowsum_s[tid] = 0.f; rowsum_s[64 + tid] = 0.f;
        rowsum_s[128 + tid] = 0.f; rowsum_s[192 + tid] = 0.f;
    }

    float acc_o[2][2][4];
    #pragma unroll
    for (int i = 0; i < 2; i++)
        #pragma unroll
        for (int j = 0; j < 2; j++)
            #pragma unroll
            for (int l = 0; l < 4; l++) acc_o[i][j][l] = 0.f;

    // hoisted Q fragments (loaded once after chunk-0 wait)
    uint32_t qf[4][2][4];
    bool qLoaded = false;

    for (int ch = 0; ch < 8; ch++) {
        const int k0 = ch * 128;
        const int kb = ch & 1;
        CP_WAIT(0);
        __syncthreads();

        if (!qLoaded) {
            qLoaded = true;
            const int arow = (lane & 7) + ((lane >> 3) & 1) * 8;
            #pragma unroll
            for (int ksi = 0; ksi < 4; ksi++) {
                const int acol = ksi * 16 + (lane >> 4) * 8;
                #pragma unroll
                for (int mt = 0; mt < 2; mt++) {
                    uint32_t off = (uint32_t)((wmS * 32 + mt * 16 + arow) * SRQ + acol) * 2;
                    LDSM4(qf[ksi][mt], sbase + Q_0 + off);
                }
            }
        }

        if (ch + 1 < 8) {
            #pragma unroll
            for (int j = 0; j < 4; j++) {
                int i = tid + j * 256, r = i >> 3, c = (i & 7) << 3;
                CP16(sbase + K_0 + (kb ^ 1) * KBUF + (uint32_t)(r * SRQ + c) * 2,
                     Kg + (size_t)(k0 + 128 + r) * 768 + c);
            }
            CP_COMMIT();
        }

        float acc_s[2][4][4];
        #pragma unroll
        for (int i = 0; i < 2; i++)
            #pragma unroll
            for (int j = 0; j < 4; j++)
                #pragma unroll
                for (int l = 0; l < 4; l++) acc_s[i][j][l] = 0.f;

        const uint32_t kbase = sbase + K_0 + kb * KBUF;
        #pragma unroll
        for (int ksi = 0; ksi < 4; ksi++) {
            const int ks = ksi * 16;
            uint32_t bf[4][2];
            const int g = lane >> 3;
            const int brow = (g >> 1) * 8 + (lane & 7);
            const int bcol = ks + (g & 1) * 8;
            #pragma unroll
            for (int np = 0; np < 2; np++) {
                uint32_t off = (uint32_t)((wnS * 32 + np * 16 + brow) * SRQ + bcol) * 2;
                uint32_t t[4];
                LDSM4(t, kbase + off);
                bf[2 * np][0] = t[0]; bf[2 * np][1] = t[1];
                bf[2 * np + 1][0] = t[2]; bf[2 * np + 1][1] = t[3];
            }
            #pragma unroll
            for (int mt = 0; mt < 2; mt++)
                #pragma unroll
                for (int nt = 0; nt < 4; nt++)
                    MMA_F16(acc_s[mt][nt], qf[ksi][mt], bf[nt]);
        }

        float2 af2[4];
        #pragma unroll
        for (int nt = 0; nt < 4; nt++)
            af2[nt] = *(const float2*)(aff + k0 + wnS * 32 + nt * 8 + qid * 2);
        float* rsb = rowsum_s + wnS * 64;
        #pragma unroll
        for (int mt = 0; mt < 2; mt++) {
            int row0 = wmS * 32 + mt * 16 + gidr;
            float rs0 = 0.f, rs1 = 0.f;
            #pragma unroll
            for (int nt = 0; nt < 4; nt++) {
                float e0 = __expf(acc_s[mt][nt][0] * SCALE);
                float e1 = __expf(acc_s[mt][nt][1] * SCALE);
                float e2 = __expf(acc_s[mt][nt][2] * SCALE);
                float e3 = __expf(acc_s[mt][nt][3] * SCALE);
                rs0 += e0 + e1; rs1 += e2 + e3;
                int col = wnS * 32 + nt * 8 + qid * 2;
                *(__half2*)(P_s + row0 * SRP + col)       = __floats2half2_rn(e0 * af2[nt].x, e1 * af2[nt].y);
                *(__half2*)(P_s + (row0 + 8) * SRP + col) = __floats2half2_rn(e2 * af2[nt].x, e3 * af2[nt].y);
            }
            rs0 += __shfl_xor_sync(0xffffffffu, rs0, 1);
            rs0 += __shfl_xor_sync(0xffffffffu, rs0, 2);
            rs1 += __shfl_xor_sync(0xffffffffu, rs1, 1);
            rs1 += __shfl_xor_sync(0xffffffffu, rs1, 2);
            if (qid == 0) {
                rsb[row0] += rs0;        // per-wnS bank: no contention
                rsb[row0 + 8] += rs1;
            }
        }
        __syncthreads();

        #pragma unroll
        for (int ks = 0; ks < 128; ks += 16) {
            uint32_t af[2][4];
            const int arow = (lane & 7) + ((lane >> 3) & 1) * 8;
            const int acol = ks + (lane >> 4) * 8;
            #pragma unroll
            for (int mt = 0; mt < 2; mt++) {
                uint32_t off = (uint32_t)((wm2 * 32 + mt * 16 + arow) * SRP + acol) * 2;
                LDSM4(af[mt], sbase + P_0 + off);
            }
            uint32_t bf[2][2];
            const int g = lane >> 3;
            const int brow = (g >> 1) * 8 + (lane & 7);
            const int bcol = ks + (g & 1) * 8;
            {
                uint32_t off = (uint32_t)((wn2 * 16 + brow) * SRP + bcol) * 2;
                uint32_t t[4];
                LDSM4(t, sbase + V_0 + off);
                bf[0][0] = t[0]; bf[0][1] = t[1]; bf[1][0] = t[2]; bf[1][1] = t[3];
            }
            #pragma unroll
            for (int mt = 0; mt < 2; mt++)
                #pragma unroll
                for (int nt = 0; nt < 2; nt++)
                    MMA_F16(acc_o[mt][nt], af[mt], bf[nt]);
        }
        __syncthreads();

        if (ch + 1 < 8) {
            #pragma unroll
            for (int j = 0; j < 4; j++) {
                int i = tid + j * 256, r = i >> 4, c = (i & 15) << 3;
                CP16(sbase + V_0 + (uint32_t)(r * SRP + c) * 2, Vg + (size_t)r * 1024 + k0 + 128 + c);
            }
            CP_COMMIT();
        }
    }

    // reduce rowsum banks
    if (tid < 64)
        rowsum_s[tid] = (rowsum_s[tid] + rowsum_s[64 + tid])
                      + (rowsum_s[128 + tid] + rowsum_s[192 + tid]);
    __syncthreads();

    #pragma unroll
    for (int mt = 0; mt < 2; mt++) {
        int row = wm2 * 32 + mt * 16 + gidr;
        float inv0 = 1.f / rowsum_s[row];
        float inv8 = 1.f / rowsum_s[row + 8];
        #pragma unroll
        for (int nt = 0; nt < 2; nt++) {
            int col = wn2 * 16 + nt * 8 + qid * 2;
            size_t o0 = ((size_t)b * 1024 + m0 + row) * 768 + h * 64 + col;
            size_t o8 = o0 + 8u * 768u;
            *(__half2*)(g_o + o0) = __floats2half2_rn(acc_o[mt][nt][0] * inv0, acc_o[mt][nt][1] * inv0);
            *(__half2*)(g_o + o8) = __floats2half2_rn(acc_o[mt][nt][2] * inv8, acc_o[mt][nt][3] * inv8);
        }
    }
}

// ======================= output projection ==================================
__global__ void __launch_bounds__(256, 2) proj_mma(const float* __restrict__ bp,
                                                   float* __restrict__ out)
{
    extern __shared__ char smem[];
    const int m0 = blockIdx.y * 128, n0 = blockIdx.x * 128;

    const __half* A = g_o + (size_t)m0 * 768;
    const __half* B = g_w + (size_t)3 * 768 * 768 + (size_t)n0 * 768;

    gemm_to_stage<128>(A, 768, B, 768, 768, smem);
    float* stage = (float*)smem;

    for (int idx = threadIdx.x; idx < 128 * 128; idx += 256) {
        int mr = idx >> 7, nc = idx & 127;
        int n = n0 + nc;
        out[(size_t)(m0 + mr) * Cdim + n] = stage[mr * 129 + nc] + bp[n];
    }
}

// ============================================================================
extern "C" void kernel_launch(void* const* d_in, const int* in_sizes, int n_in,
                              void* d_out, int out_size)
{
    (void)in_sizes; (void)n_in; (void)out_size;
    const float* xq = (const float*)d_in[0];
    const float* xk = (const float*)d_in[1];
    const float* xv = (const float*)d_in[2];
    const float* et = (const float*)d_in[3];
    const float* Wq = (const float*)d_in[4];
    const float* Wk = (const float*)d_in[5];
    const float* Wv = (const float*)d_in[6];
    const float* Wp = (const float*)d_in[7];
    const float* bp = (const float*)d_in[8];

    float* out     = (float*)d_out;
    float* out_x   = out;
    float* out_as  = out + (size_t)Bsz * Ntok * Cdim;
    float* out_aff = out_as + (size_t)Bsz * Ntok * Ntok;

    const int SMEM_BIG = 110592;
    const int SMEM_FLASH = 81920;   // +4 rowsum banks (RS0 + 1024)
    cudaFuncSetAttribute(qkv_mma,      cudaFuncAttributeMaxDynamicSharedMemorySize, SMEM_BIG);
    cudaFuncSetAttribute(attnsave_mma, cudaFuncAttributeMaxDynamicSharedMemorySize, SMEM_BIG);
    cudaFuncSetAttribute(flash_fused,  cudaFuncAttributeMaxDynamicSharedMemorySize, SMEM_FLASH);
    cudaFuncSetAttribute(proj_mma,     cudaFuncAttributeMaxDynamicSharedMemorySize, SMEM_BIG);

    static cudaStream_t s1 = nullptr;
    static cudaEvent_t eQK = nullptr, eAff = nullptr, eA = nullptr;
    if (!s1) {
        cudaStreamCreateWithFlags(&s1, cudaStreamNonBlocking);
        cudaEventCreateWithFlags(&eQK, cudaEventDisableTiming);
        cudaEventCreateWithFlags(&eAff, cudaEventDisableTiming);
        cudaEventCreateWithFlags(&eA, cudaEventDisableTiming);
    }

    const int NX4 = 8192 * 768 / 4, NW4 = 768 * 768 / 4;
    cvtX_kernel<<<dim3((NX4 + 255) / 256, 1, 3), 256>>>((const float4*)xq, (const float4*)xk,
                                                        (const float4*)xv, NX4);
    cvtW_kernel<<<dim3((NW4 + 255) / 256, 1, 4), 256>>>((const float4*)Wq, (const float4*)Wk,
                                                        (const float4*)Wv, (const float4*)Wp, NW4);

    qkv_mma<<<dim3(6, 64, 2), 256, SMEM_BIG>>>(0);
    cudaEventRecord(eQK, 0);

    cudaStreamWaitEvent(s1, eQK, 0);
    aff_kernel<<<(Bsz * Ntok) / 8, 256, 0, s1>>>(et, out_aff);
    cudaEventRecord(eAff, s1);
    attnsave_mma<<<dim3(8, 8, Bsz), 256, SMEM_BIG, s1>>>(out_as);
    cudaEventRecord(eA, s1);

    qkv_mma<<<dim3(6, 64, 1), 256, SMEM_BIG>>>(2);
    cudaStreamWaitEvent(0, eAff, 0);
    flash_fused<<<dim3(16, BH), 256, SMEM_FLASH>>>();
    proj_mma<<<dim3(6, 64, 1), 256, SMEM_BIG>>>(bp, out_x);

    cudaStreamWaitEvent(0, eA, 0);
}